// round 13
// baseline (speedup 1.0000x reference)
#include <cuda_runtime.h>
#include <cstdint>

#define NB     150
#define NBA    160         // padded, mult of 4; entries >=150 inert (area=1e30, sorted last)
#define NC     80
#define BATCH  8
#define EPSF   1e-6f
#define NT     512         // 2 threads per anchor -> 256 anchors per block
#define APB    256

#define N_S 17328
#define N_M 4332
#define N_L 1083
#define B_S 68
#define B_M 17
#define B_L 5
#define BPB (B_S+B_M+B_L)  // 90
#define GRID (BPB*BATCH)   // 720

__device__ double g_pg[GRID];
__device__ double g_pc[GRID];
__device__ double g_pk[GRID];
__device__ unsigned g_count = 0;

__device__ __forceinline__ float softplus_f(float x) {
    return fmaxf(x, 0.0f) + __logf(1.0f + __expf(-fabsf(x)));
}

__global__ __launch_bounds__(NT, 2)
void fused_loss_kernel(const float* __restrict__ p0,  const float* __restrict__ pd0, const float* __restrict__ l0,
                       const float* __restrict__ p1,  const float* __restrict__ pd1, const float* __restrict__ l1,
                       const float* __restrict__ p2,  const float* __restrict__ pd2, const float* __restrict__ l2,
                       const float* __restrict__ b0,  const float* __restrict__ b1,  const float* __restrict__ b2,
                       float* __restrict__ out)
{
    const int tid   = threadIdx.x;
    const int bid   = blockIdx.x;
    const int batch = bid / BPB;
    const int r     = bid % BPB;

    const float *P, *PD, *L, *BX;
    int n, blk;
    if (r < B_S)            { P = p0; PD = pd0; L = l0; BX = b0; n = N_S; blk = r; }
    else if (r < B_S + B_M) { P = p1; PD = pd1; L = l1; BX = b1; n = N_M; blk = r - B_S; }
    else                    { P = p2; PD = pd2; L = l2; BX = b2; n = N_L; blk = r - B_S - B_M; }

    __shared__ float4 rb[NBA];          // raw corners
    __shared__ float  ra[NBA];          // raw areas
    __shared__ float4 sbx[NBA];         // area-sorted corners
    __shared__ float  sa [NBA];         // ascending areas
    __shared__ float  sn3[NBA];         // -area/3 (sorted order)
    __shared__ unsigned char perm[APB]; // anchor permutation (area buckets)
    __shared__ unsigned char keys[APB];
    __shared__ int hist[32];

    // ---- phase 1: raw boxes + hist init ----
    for (int i = tid; i < NBA; i += NT) {
        if (i < NB) {
            float4 v = reinterpret_cast<const float4*>(BX)[batch * NB + i];
            float4 c;
            c.x = v.x - 0.5f * v.z;  c.y = v.y - 0.5f * v.w;
            c.z = v.x + 0.5f * v.z;  c.w = v.y + 0.5f * v.w;
            rb[i] = c;
            ra[i] = v.z * v.w;
        } else {
            rb[i] = make_float4(2e30f, 2e30f, 2e30f, 2e30f);
            ra[i] = 1e30f;                       // sorts last, always outside any window
        }
    }
    if (tid < 32) hist[tid] = 0;
    __syncthreads();

    // ---- phase 2a: anchor area keys (bucket by fp32 exponent of a1) ----
    if (tid < APB) {
        const int jj = blk * APB + tid;
        float aa = 1.0f;
        if (jj < n) {
            const float* PDp = PD + (size_t)(batch * n + jj) * 85;
            aa = PDp[2] * PDp[3];
        }
        int key = (int)((__float_as_uint(aa) >> 23) & 0xFFu) - 127;
        key = max(0, min(31, key));
        keys[tid] = (unsigned char)key;
        atomicAdd(&hist[key], 1);
    }

    // ---- phase 2b: rank-sort boxes by area (validated R9 code; halves of NBA/2) ----
    {
        const bool act = (tid < 2 * NBA);
        const int  i   = act ? (tid >> 1) : 0;
        const int  h   = tid & 1;
        int rk = 0;
        if (act) {
            const float ai = ra[i];
            const int j0 = h * (NBA / 2);
            for (int jj = j0; jj < j0 + NBA / 2; jj++) {
                const float aj = ra[jj];
                rk += (aj < ai || (aj == ai && jj < i)) ? 1 : 0;
            }
        }
        rk += __shfl_xor_sync(0xFFFFFFFFu, rk, 1);
        if (act && h == 0) {
            sbx[rk] = rb[i];
            sa [rk] = ra[i];
            sn3[rk] = -ra[i] * (1.0f / 3.0f);
        }
    }
    __syncthreads();

    // ---- phase 3: prefix + scatter ranks ----
    if (tid == 0) {
        int acc = 0;
        #pragma unroll
        for (int b = 0; b < 32; b++) { const int c = hist[b]; hist[b] = acc; acc += c; }
    }
    __syncthreads();
    if (tid < APB) {
        const int rkk = atomicAdd(&hist[keys[tid]], 1);
        perm[rkk] = (unsigned char)tid;
    }
    __syncthreads();

    // ---- phase 4: permuted anchor headers (pair lanes share an anchor) ----
    const int slot   = perm[tid >> 1];
    const int j      = blk * APB + slot;
    const bool valid = (j < n);
    const int base   = batch * n + j;
    const int half   = tid & 1;

    float px1 = 0.f, py1 = 0.f, px2 = 0.f, py2 = 0.f, a1 = 0.f;
    float pconf = 0.f, obj = 0.f, mix = 0.f;
    if (valid) {
        const float* PDp = PD + (size_t)base * 85;
        const float pcx = PDp[0], pcy = PDp[1], pw = PDp[2], ph = PDp[3];
        px1 = pcx - 0.5f * pw;  px2 = pcx + 0.5f * pw;
        py1 = pcy - 0.5f * ph;  py2 = pcy + 0.5f * ph;
        a1  = pw * ph;
        pconf = P[(size_t)base * 85 + 4];
        const float2 om = *reinterpret_cast<const float2*>(L + (size_t)base * 86 + 4);
        obj = om.x;  mix = om.y;
    }

    // ---- phase 5: per-anchor area window (validated R9 margins), warp-union ----
    const float t   = a1 * (1.0f / 3.0f);
    const float tlo = a1 * 0.4975f;   // a1/2.01
    const float thi = a1 * 2.015f;
    int lo = NBA, hi = 0;
    if (valid) {
        int l = 0, rr = NBA;
        while (l < rr) { const int mid = (l + rr) >> 1; if (sa[mid] < tlo) l = mid + 1; else rr = mid; }
        lo = l;
        rr = NBA;
        while (l < rr) { const int mid = (l + rr) >> 1; if (sa[mid] <= thi) l = mid + 1; else rr = mid; }
        hi = l;
    }
    int ulo = lo, uhi = hi;
    #pragma unroll
    for (int o = 16; o > 0; o >>= 1) {
        ulo = min(ulo, __shfl_xor_sync(0xFFFFFFFFu, ulo, o));
        uhi = max(uhi, __shfl_xor_sync(0xFFFFFFFFu, uhi, o));
    }
    ulo &= ~3;                       // round to group of 4; extra boxes are exactly evaluated
    uhi = min((uhi + 3) & ~3, NBA);  // accesses <= uhi-4+half+2 < NBA

    // ---- phase 6: hot loop, warp-uniform bounds, broadcast LDS ----
    // hit <=> iw*ih - barea/3 >= a1/3  (w,h>=1 => union>=1). iw unclamped: iw<0 never false-hits.
    float m0 = -1e30f, m1 = -1e30f;
    for (int i = ulo + half; i < uhi; i += 4) {
        const float4 q0 = sbx[i];
        const float  s0 = sn3[i];
        const float4 q1 = sbx[i + 2];
        const float  s1 = sn3[i + 2];
        {
            const float iw = fminf(px2, q0.z) - fmaxf(px1, q0.x);
            const float ih = fmaxf(fminf(py2, q0.w) - fmaxf(py1, q0.y), 0.0f);
            m0 = fmaxf(m0, fmaf(iw, ih, s0));
        }
        {
            const float iw = fminf(px2, q1.z) - fmaxf(px1, q1.x);
            const float ih = fmaxf(fminf(py2, q1.w) - fmaxf(py1, q1.y), 0.0f);
            m1 = fmaxf(m1, fmaf(iw, ih, s1));
        }
    }
    float m = fmaxf(m0, m1);
    m = fmaxf(m, __shfl_xor_sync(0xFFFFFFFFu, m, 1));   // combine the pair

    if (half) { obj = 0.0f; mix = 0.0f; }

    // ---- per-anchor focal-conf / giou (float per-anchor terms: deterministic) ----
    float lgf = 0.0f, lcf = 0.0f, lkf = 0.0f;

    const float sig = 1.0f / (1.0f + __expf(-pconf));
    const float bce = softplus_f(pconf) - pconf * obj;
    const float d   = obj - sig;
    const float fl  = bce * d * d;

    float coef;
    if (obj > 0.0f) {
        coef = obj;
        const float2 lxy = *reinterpret_cast<const float2*>(L + (size_t)base * 86);
        const float2 lwh = *reinterpret_cast<const float2*>(L + (size_t)base * 86 + 2);
        const float lx1 = lxy.x - 0.5f * lwh.x, lx2 = lxy.x + 0.5f * lwh.x;
        const float ly1 = lxy.y - 0.5f * lwh.y, ly2 = lxy.y + 0.5f * lwh.y;
        const float a2  = lwh.x * lwh.y;

        float iw = fminf(px2, lx2) - fmaxf(px1, lx1);
        float ih = fminf(py2, ly2) - fmaxf(py1, ly1);
        iw = fmaxf(iw, 0.0f);  ih = fmaxf(ih, 0.0f);
        const float inter = iw * ih;
        const float uni   = a1 + a2 - inter;
        const float iou   = inter / fmaxf(uni, EPSF);

        float ew = fmaxf(px2, lx2) - fminf(px1, lx1);
        float eh = fmaxf(py2, ly2) - fminf(py1, ly1);
        ew = fmaxf(ew, 0.0f);  eh = fmaxf(eh, 0.0f);
        const float ea   = ew * eh;
        const float giou = iou - (ea - uni) / fmaxf(ea, EPSF);

        lgf = obj * (1.0f - giou) * mix;
    } else {
        coef = (m >= t) ? 0.0f : 1.0f;
    }
    lcf = coef * fl * mix;
    const float objmix = (valid && obj > 0.0f) ? obj * mix : 0.0f;

    // ---- cooperative class-BCE ----
    const int lane = tid & 31;
    {
        unsigned mask = __ballot_sync(0xFFFFFFFFu, objmix > 0.0f);
        while (mask) {
            const int src = __ffs(mask) - 1;
            mask &= mask - 1;
            const int   sbase = __shfl_sync(0xFFFFFFFFu, base, src);
            const float wgt   = __shfl_sync(0xFFFFFFFFu, objmix, src);
            const float* Pc = P + (size_t)sbase * 85 + 5;
            const float* Lc = L + (size_t)sbase * 86 + 6;
            float s = 0.0f;
            #pragma unroll
            for (int c = lane; c < NC; c += 32) {
                const float xx = Pc[c];
                s += softplus_f(xx) - xx * Lc[c];
            }
            #pragma unroll
            for (int o = 16; o > 0; o >>= 1) s += __shfl_down_sync(0xFFFFFFFFu, s, o);
            if (lane == 0) lkf += wgt * s;
        }
    }

    // ---- block reduction in double (permutation-order invariant to ~1e-15) ----
    double lg = (double)lgf, lc = (double)lcf, lk = (double)lkf;
    #pragma unroll
    for (int o = 16; o > 0; o >>= 1) {
        lg += __shfl_down_sync(0xFFFFFFFFu, lg, o);
        lc += __shfl_down_sync(0xFFFFFFFFu, lc, o);
        lk += __shfl_down_sync(0xFFFFFFFFu, lk, o);
    }
    __shared__ double rg[NT/32], rc[NT/32], rk2[NT/32];
    __shared__ bool s_last;
    const int w = tid >> 5;
    if (lane == 0) { rg[w] = lg; rc[w] = lc; rk2[w] = lk; }
    __syncthreads();

    if (tid == 0) {
        double sg = 0.0, sc = 0.0, sk = 0.0;
        #pragma unroll
        for (int i = 0; i < NT/32; i++) { sg += rg[i]; sc += rc[i]; sk += rk2[i]; }
        g_pg[bid] = sg;
        g_pc[bid] = sc;
        g_pk[bid] = sk;
        __threadfence();
        const unsigned prev = atomicAdd(&g_count, 1u);
        s_last = (prev == GRID - 1);
    }
    __syncthreads();

    if (s_last) {
        double dg = 0.0, dc = 0.0, dk = 0.0;
        for (int i = tid; i < GRID; i += NT) {
            dg += g_pg[i];  dc += g_pc[i];  dk += g_pk[i];
        }
        #pragma unroll
        for (int o = 16; o > 0; o >>= 1) {
            dg += __shfl_down_sync(0xFFFFFFFFu, dg, o);
            dc += __shfl_down_sync(0xFFFFFFFFu, dc, o);
            dk += __shfl_down_sync(0xFFFFFFFFu, dk, o);
        }
        __shared__ double zg[NT/32], zc[NT/32], zk[NT/32];
        if (lane == 0) { zg[w] = dg; zc[w] = dc; zk[w] = dk; }
        __syncthreads();
        if (tid == 0) {
            double fg = 0.0, fc = 0.0, fk = 0.0;
            #pragma unroll
            for (int i = 0; i < NT/32; i++) { fg += zg[i]; fc += zc[i]; fk += zk[i]; }
            const float og = (float)(fg / (double)BATCH);
            const float oc = (float)(fc / (double)BATCH);
            const float ok = (float)(fk / (double)BATCH);
            out[0] = og + oc + ok;
            out[1] = og;
            out[2] = oc;
            out[3] = ok;
            g_count = 0;
        }
    }
}

extern "C" void kernel_launch(void* const* d_in, const int* in_sizes, int n_in,
                              void* d_out, int out_size)
{
    // harness order (dict insertion order, interleaved per scale):
    // 0: p_s   1: p_d_s  2: label_sbbox
    // 3: p_m   4: p_d_m  5: label_mbbox
    // 6: p_l   7: p_d_l  8: label_lbbox
    // 9: sbboxes  10: mbboxes  11: lbboxes
    fused_loss_kernel<<<GRID, NT>>>(
        (const float*)d_in[0], (const float*)d_in[1], (const float*)d_in[2],
        (const float*)d_in[3], (const float*)d_in[4], (const float*)d_in[5],
        (const float*)d_in[6], (const float*)d_in[7], (const float*)d_in[8],
        (const float*)d_in[9], (const float*)d_in[10], (const float*)d_in[11],
        (float*)d_out);
}

// round 14
// speedup vs baseline: 1.3333x; 1.3333x over previous
#include <cuda_runtime.h>
#include <cstdint>

#define NB     150
#define NB_PAD 152         // padded with inert dummies; each pair-lane scans 76
#define HALF   76          // divisible by 4
#define NC     80
#define BATCH  8
#define EPSF   1e-6f
#define NT     512
#define APT    2           // anchors per thread
#define APB    512         // anchors per block (256 pairs x 2 anchors)

// anchors per batch, per scale
#define N_S 17328
#define N_M 4332
#define N_L 1083
#define B_S 34             // ceil(N_S/APB)
#define B_M 9
#define B_L 3
#define BPB (B_S+B_M+B_L)  // 46
#define GRID (BPB*BATCH)   // 368

__device__ double g_pg[GRID];
__device__ double g_pc[GRID];
__device__ double g_pk[GRID];
__device__ unsigned g_count = 0;   // reset by finishing block each run

__device__ __forceinline__ float softplus_f(float x) {
    return fmaxf(x, 0.0f) + __logf(1.0f + __expf(-fabsf(x)));
}

__global__ __launch_bounds__(NT)
void fused_loss_kernel(const float* __restrict__ p0,  const float* __restrict__ pd0, const float* __restrict__ l0,
                       const float* __restrict__ p1,  const float* __restrict__ pd1, const float* __restrict__ l1,
                       const float* __restrict__ p2,  const float* __restrict__ pd2, const float* __restrict__ l2,
                       const float* __restrict__ b0,  const float* __restrict__ b1,  const float* __restrict__ b2,
                       float* __restrict__ out)
{
    const int tid   = threadIdx.x;
    const int bid   = blockIdx.x;
    const int batch = bid / BPB;
    const int r     = bid % BPB;

    const float *P, *PD, *L, *BX;
    int n, blk;
    if (r < B_S)            { P = p0; PD = pd0; L = l0; BX = b0; n = N_S; blk = r; }
    else if (r < B_S + B_M) { P = p1; PD = pd1; L = l1; BX = b1; n = N_M; blk = r - B_S; }
    else                    { P = p2; PD = pd2; L = l2; BX = b2; n = N_L; blk = r - B_S - B_M; }

    // ---- batch boxes -> shared as (x1,y1,x2,y2) + (-2*area/3); inert dummies in the pad ----
    __shared__ float4 sb[NB_PAD];
    __shared__ float  sn32[NB_PAD];     // -2*(w*h)/3
    for (int i = tid; i < NB_PAD; i += NT) {
        if (i < NB) {
            float4 v = reinterpret_cast<const float4*>(BX)[batch * NB + i];
            float4 c;
            c.x = v.x - 0.5f * v.z;  c.y = v.y - 0.5f * v.w;
            c.z = v.x + 0.5f * v.z;  c.w = v.y + 0.5f * v.w;
            sb[i]   = c;
            sn32[i] = -(v.z * v.w) * (2.0f / 3.0f);
        } else {
            sb[i]   = make_float4(2e30f, 2e30f, 2e30f, 2e30f);  // iw<0, ihs=0 -> never triggers
            sn32[i] = -2e30f;
        }
    }
    __syncthreads();

    // ---- decomposition: pair (2k,2k+1) shares 2 anchors; each lane scans its half of boxes ----
    const int q    = tid >> 1;          // pair index 0..255
    const int half = tid & 1;           // 0 -> boxes [0,76), 1 -> [76,152)

    int   base[APT];  bool valid[APT];
    float px1[APT], py1[APT], px2[APT], py2[APT], a1[APT];
    float pconf[APT], obj[APT], mix[APT];

    #pragma unroll
    for (int a = 0; a < APT; a++) {
        const int j = blk * APB + q + a * 256;
        valid[a] = (j < n);
        base[a]  = batch * n + (valid[a] ? j : 0);
        if (valid[a]) {
            const float* PDp = PD + (size_t)base[a] * 85;
            const float pcx = PDp[0], pcy = PDp[1], pw = PDp[2], ph = PDp[3];
            px1[a] = pcx - 0.5f * pw;  px2[a] = pcx + 0.5f * pw;
            py1[a] = pcy - 0.5f * ph;  py2[a] = pcy + 0.5f * ph;
            a1[a]  = pw * ph;
            pconf[a] = P[(size_t)base[a] * 85 + 4];
            const float2 om = *reinterpret_cast<const float2*>(L + (size_t)base[a] * 86 + 4);
            obj[a] = om.x;  mix[a] = om.y;
        } else {
            px1[a]=px2[a]=py1[a]=py2[a]=a1[a]=pconf[a]=obj[a]=mix[a]=0.0f;
        }
    }

    // ---- hot loop: iou >= 0.5  <=>  iw*(2*max(ih,0)) - 2*barea/3 >= 2*a1/3 ----
    // ihs = ih + |ih| = 2*max(ih,0)  (fma pipe). iw unclamped: iw<0 never false-hits.
    // FULLY UNROLLED: 19 groups x 4 boxes x 2 anchors; all LDS at [base+imm].
    const float4* __restrict__ sbp = sb + half * HALF;
    const float4* __restrict__ s3p = reinterpret_cast<const float4*>(sn32 + half * HALF);
    float m00 = -1e30f, m01 = -1e30f;   // anchor 0, two chains
    float m10 = -1e30f, m11 = -1e30f;   // anchor 1, two chains
    #pragma unroll
    for (int g = 0; g < HALF / 4; g++) {
        const float4 q0 = sbp[4 * g];
        const float4 q1 = sbp[4 * g + 1];
        const float4 q2 = sbp[4 * g + 2];
        const float4 q3 = sbp[4 * g + 3];
        const float4 s4 = s3p[g];
        // anchor 0
        {
            float iw, ih, ihs;
            iw = fminf(px2[0], q0.z) - fmaxf(px1[0], q0.x);
            ih = fminf(py2[0], q0.w) - fmaxf(py1[0], q0.y);  ihs = ih + fabsf(ih);
            m00 = fmaxf(m00, fmaf(iw, ihs, s4.x));
            iw = fminf(px2[0], q1.z) - fmaxf(px1[0], q1.x);
            ih = fminf(py2[0], q1.w) - fmaxf(py1[0], q1.y);  ihs = ih + fabsf(ih);
            m01 = fmaxf(m01, fmaf(iw, ihs, s4.y));
            iw = fminf(px2[0], q2.z) - fmaxf(px1[0], q2.x);
            ih = fminf(py2[0], q2.w) - fmaxf(py1[0], q2.y);  ihs = ih + fabsf(ih);
            m00 = fmaxf(m00, fmaf(iw, ihs, s4.z));
            iw = fminf(px2[0], q3.z) - fmaxf(px1[0], q3.x);
            ih = fminf(py2[0], q3.w) - fmaxf(py1[0], q3.y);  ihs = ih + fabsf(ih);
            m01 = fmaxf(m01, fmaf(iw, ihs, s4.w));
        }
        // anchor 1
        {
            float iw, ih, ihs;
            iw = fminf(px2[1], q0.z) - fmaxf(px1[1], q0.x);
            ih = fminf(py2[1], q0.w) - fmaxf(py1[1], q0.y);  ihs = ih + fabsf(ih);
            m10 = fmaxf(m10, fmaf(iw, ihs, s4.x));
            iw = fminf(px2[1], q1.z) - fmaxf(px1[1], q1.x);
            ih = fminf(py2[1], q1.w) - fmaxf(py1[1], q1.y);  ihs = ih + fabsf(ih);
            m11 = fmaxf(m11, fmaf(iw, ihs, s4.y));
            iw = fminf(px2[1], q2.z) - fmaxf(px1[1], q2.x);
            ih = fminf(py2[1], q2.w) - fmaxf(py1[1], q2.y);  ihs = ih + fabsf(ih);
            m10 = fmaxf(m10, fmaf(iw, ihs, s4.z));
            iw = fminf(px2[1], q3.z) - fmaxf(px1[1], q3.x);
            ih = fminf(py2[1], q3.w) - fmaxf(py1[1], q3.y);  ihs = ih + fabsf(ih);
            m11 = fmaxf(m11, fmaf(iw, ihs, s4.w));
        }
    }
    float m[APT];
    m[0] = fmaxf(m00, m01);
    m[1] = fmaxf(m10, m11);
    m[0] = fmaxf(m[0], __shfl_xor_sync(0xFFFFFFFFu, m[0], 1));   // combine pair halves
    m[1] = fmaxf(m[1], __shfl_xor_sync(0xFFFFFFFFu, m[1], 1));

    if (half) {
        #pragma unroll
        for (int a = 0; a < APT; a++) { obj[a] = 0.0f; mix[a] = 0.0f; }  // odd lane inert
    }

    // ---- per-anchor focal-conf / giou ----
    float lg = 0.0f, lc = 0.0f, lk = 0.0f;
    float objmix[APT];

    #pragma unroll
    for (int a = 0; a < APT; a++) {
        const float x   = pconf[a];
        const float sig = 1.0f / (1.0f + __expf(-x));
        const float bce = softplus_f(x) - x * obj[a];
        const float d   = obj[a] - sig;
        const float fl  = bce * d * d;

        float coef;
        if (obj[a] > 0.0f) {
            coef = obj[a];
            // ---- GIoU vs label box (rare path) ----
            const float2 lxy = *reinterpret_cast<const float2*>(L + (size_t)base[a] * 86);
            const float2 lwh = *reinterpret_cast<const float2*>(L + (size_t)base[a] * 86 + 2);
            const float lx1 = lxy.x - 0.5f * lwh.x, lx2 = lxy.x + 0.5f * lwh.x;
            const float ly1 = lxy.y - 0.5f * lwh.y, ly2 = lxy.y + 0.5f * lwh.y;
            const float a2  = lwh.x * lwh.y;

            float iw = fminf(px2[a], lx2) - fmaxf(px1[a], lx1);
            float ih = fminf(py2[a], ly2) - fmaxf(py1[a], ly1);
            iw = fmaxf(iw, 0.0f);  ih = fmaxf(ih, 0.0f);
            const float inter = iw * ih;
            const float uni   = a1[a] + a2 - inter;
            const float iou   = inter / fmaxf(uni, EPSF);

            float ew = fmaxf(px2[a], lx2) - fminf(px1[a], lx1);
            float eh = fmaxf(py2[a], ly2) - fminf(py1[a], ly1);
            ew = fmaxf(ew, 0.0f);  eh = fmaxf(eh, 0.0f);
            const float ea   = ew * eh;
            const float giou = iou - (ea - uni) / fmaxf(ea, EPSF);

            lg += obj[a] * (1.0f - giou) * mix[a];
        } else {
            coef = (m[a] >= a1[a] * (2.0f / 3.0f)) ? 0.0f : 1.0f;   // noobj * (iou_max < 0.5)
        }
        lc += coef * fl * mix[a];
        objmix[a] = (valid[a] && obj[a] > 0.0f) ? obj[a] * mix[a] : 0.0f;
    }

    // ---- cooperative class-BCE: whole warp serves each obj anchor ----
    const int lane = tid & 31;
    #pragma unroll
    for (int a = 0; a < APT; a++) {
        unsigned mask = __ballot_sync(0xFFFFFFFFu, objmix[a] > 0.0f);
        while (mask) {
            const int src = __ffs(mask) - 1;
            mask &= mask - 1;
            const int   sbase = __shfl_sync(0xFFFFFFFFu, base[a], src);
            const float wgt   = __shfl_sync(0xFFFFFFFFu, objmix[a], src);
            const float* Pc = P + (size_t)sbase * 85 + 5;
            const float* Lc = L + (size_t)sbase * 86 + 6;
            float s = 0.0f;
            #pragma unroll
            for (int c = lane; c < NC; c += 32) {
                const float xx = Pc[c];
                s += softplus_f(xx) - xx * Lc[c];
            }
            #pragma unroll
            for (int o = 16; o > 0; o >>= 1) s += __shfl_down_sync(0xFFFFFFFFu, s, o);
            if (lane == 0) lk += wgt * s;
        }
    }

    // ---- block reduction (float warp-level, as validated in R12) ----
    #pragma unroll
    for (int o = 16; o > 0; o >>= 1) {
        lg += __shfl_down_sync(0xFFFFFFFFu, lg, o);
        lc += __shfl_down_sync(0xFFFFFFFFu, lc, o);
        lk += __shfl_down_sync(0xFFFFFFFFu, lk, o);
    }
    __shared__ float rg[NT/32], rc[NT/32], rk2[NT/32];
    __shared__ bool s_last;
    const int w = tid >> 5;
    if (lane == 0) { rg[w] = lg; rc[w] = lc; rk2[w] = lk; }
    __syncthreads();

    if (tid == 0) {
        float sg = 0.0f, sc = 0.0f, sk = 0.0f;
        #pragma unroll
        for (int i = 0; i < NT/32; i++) { sg += rg[i]; sc += rc[i]; sk += rk2[i]; }
        g_pg[bid] = (double)sg;
        g_pc[bid] = (double)sc;
        g_pk[bid] = (double)sk;
        __threadfence();
        const unsigned prev = atomicAdd(&g_count, 1u);
        s_last = (prev == GRID - 1);
    }
    __syncthreads();

    // ---- last block: reduce all partials, write outputs, reset counter ----
    if (s_last) {
        double dg = 0.0, dc = 0.0, dk = 0.0;
        for (int i = tid; i < GRID; i += NT) {
            dg += g_pg[i];  dc += g_pc[i];  dk += g_pk[i];
        }
        #pragma unroll
        for (int o = 16; o > 0; o >>= 1) {
            dg += __shfl_down_sync(0xFFFFFFFFu, dg, o);
            dc += __shfl_down_sync(0xFFFFFFFFu, dc, o);
            dk += __shfl_down_sync(0xFFFFFFFFu, dk, o);
        }
        __shared__ double zg[NT/32], zc[NT/32], zk[NT/32];
        if (lane == 0) { zg[w] = dg; zc[w] = dc; zk[w] = dk; }
        __syncthreads();
        if (tid == 0) {
            double fg = 0.0, fc = 0.0, fk = 0.0;
            #pragma unroll
            for (int i = 0; i < NT/32; i++) { fg += zg[i]; fc += zc[i]; fk += zk[i]; }
            const float og = (float)(fg / (double)BATCH);
            const float oc = (float)(fc / (double)BATCH);
            const float ok = (float)(fk / (double)BATCH);
            out[0] = og + oc + ok;
            out[1] = og;
            out[2] = oc;
            out[3] = ok;
            g_count = 0;           // restore state for next graph replay
        }
    }
}

extern "C" void kernel_launch(void* const* d_in, const int* in_sizes, int n_in,
                              void* d_out, int out_size)
{
    // harness order (dict insertion order, interleaved per scale):
    // 0: p_s   1: p_d_s  2: label_sbbox
    // 3: p_m   4: p_d_m  5: label_mbbox
    // 6: p_l   7: p_d_l  8: label_lbbox
    // 9: sbboxes  10: mbboxes  11: lbboxes
    fused_loss_kernel<<<GRID, NT>>>(
        (const float*)d_in[0], (const float*)d_in[1], (const float*)d_in[2],
        (const float*)d_in[3], (const float*)d_in[4], (const float*)d_in[5],
        (const float*)d_in[6], (const float*)d_in[7], (const float*)d_in[8],
        (const float*)d_in[9], (const float*)d_in[10], (const float*)d_in[11],
        (float*)d_out);
}